// round 13
// baseline (speedup 1.0000x reference)
#include <cuda_runtime.h>
#include <math.h>

#define II 64
#define HH 1408
#define OO 64
#define NN 1536
#define DD 8
#define NG 24
#define CC2 (HH + OO)   // 1472
#define YB2 88          // stage2 y-blocks (16 rows each)

typedef unsigned long long ull;

// ---------------- device scratch ----------------
__device__ float g_post_in[II * DD];
__device__ float g_post_hid[HH * DD];
__device__ float g_gi_pre1[II * NG];
__device__ float g_gi_post1[HH * NG];
__device__ float g_gi_pre2[HH * NG];
__device__ float g_gi_post2[CC2 * NG];
__device__ float g_gi_post3[HH * NG];
__device__ float g_csum1[HH * DD];
__device__ float g_csum2p[YB2 * 64 * DD];    // stage2 partials [yb][o][d]
__device__ unsigned g_bits[48 * NN];         // mask word[r/32][col], bit r%32

// ---------------- packed f32x2 helpers ----------------
__device__ __forceinline__ ull pk2(float lo, float hi) {
    ull r;
    asm("mov.b64 %0, {%1, %2};" : "=l"(r) : "r"(__float_as_uint(lo)), "r"(__float_as_uint(hi)));
    return r;
}
__device__ __forceinline__ void up2(ull v, float& lo, float& hi) {
    unsigned a, b;
    asm("mov.b64 {%0, %1}, %2;" : "=r"(a), "=r"(b) : "l"(v));
    lo = __uint_as_float(a); hi = __uint_as_float(b);
}
__device__ __forceinline__ ull ffma2_(ull a, ull b, ull c) {
    ull r;
    asm("fma.rn.f32x2 %0, %1, %2, %3;" : "=l"(r) : "l"(a), "l"(b), "l"(c));
    return r;
}
__device__ __forceinline__ ull add2_(ull a, ull b) {
    ull r;
    asm("add.rn.f32x2 %0, %1, %2;" : "=l"(r) : "l"(a), "l"(b));
    return r;
}

// ---------------- fast activations ----------------
__device__ __forceinline__ float ftanh(float x) {
    float y;
    asm("tanh.approx.f32 %0, %1;" : "=f"(y) : "f"(x));
    return y;
}
__device__ __forceinline__ float fsig(float x) {
    return fmaf(0.5f, ftanh(0.5f * x), 0.5f);
}

// Eigen/XLA-style f32 rational tanh (reference-matching saturation)
__device__ __forceinline__ float eigen_tanh(float x) {
    const float mx = 7.90531110763549805f;
    float xc = fminf(fmaxf(x, -mx), mx);
    float x2 = xc * xc;
    float p = -2.76076847742355e-16f;
    p = fmaf(x2, p, 2.00018790482477e-13f);
    p = fmaf(x2, p, -8.60467152213735e-11f);
    p = fmaf(x2, p, 5.12229709037114e-08f);
    p = fmaf(x2, p, 1.48572235717979e-05f);
    p = fmaf(x2, p, 6.37261928875436e-04f);
    p = fmaf(x2, p, 4.89352455891786e-03f);
    p = xc * p;
    float q = 1.19825839466702e-06f;
    q = fmaf(x2, q, 1.18534705686654e-04f);
    q = fmaf(x2, q, 2.26843463243900e-03f);
    q = fmaf(x2, q, 4.89352518554385e-03f);
    float r = p / q;
    if (fabsf(x) < 0.0004f) r = x;
    return r;
}

// ---------------- Whh pack: sw[p*8+k] = (W[2p][k], W[2p+1][k]), sb pairs ----
__device__ __forceinline__ void pack_whh(const float* __restrict__ W, const float* __restrict__ b,
                                         ull* sw, ull* sb, int t, int nt) {
    for (int e = t; e < 96; e += nt) {
        int p = e >> 3, k = e & 7;
        sw[e] = pk2(W[(2 * p) * 8 + k], W[(2 * p + 1) * 8 + k]);
    }
    for (int e = t; e < 12; e += nt) sb[e] = pk2(b[2 * e], b[2 * e + 1]);
}

// ---------------- K1: setup mega-kernel ----------------
// blocks [0,144): adj dtype detect + coalesced ballot bitpack (1 warp = 32x32 tile)
// block  144:     post_in + gi_pre1
// blocks [145,211): gi_post1
// blocks [211,211+208): out_hid boundary copy (if present)
__global__ __launch_bounds__(512) void k_setup(
    const void* __restrict__ adj, const float* __restrict__ obs,
    const float* __restrict__ nW_in, const float* __restrict__ nb_in,
    const float* __restrict__ Wih1, const float* __restrict__ bih1,
    const float* __restrict__ post0, const float* __restrict__ rew,
    const float* __restrict__ hid0,
    float* __restrict__ out_post, float* __restrict__ out_hid) {
    int b = blockIdx.x, t = threadIdx.x;
    if (b < 144) {
        __shared__ int s_bad[4], s_cnt[4], s_esz;
        if (t < 4) { s_bad[t] = 0; s_cnt[t] = 0; }
        __syncthreads();
        int lb[4] = {0, 0, 0, 0}, lc[4] = {0, 0, 0, 0};
        for (int i = t; i < 1600; i += 512) {
            int nz0 = ((const unsigned char*)adj)[i] != 0;
            int nz1 = ((const unsigned short*)adj)[i] != 0;
            int nz2 = ((const unsigned int*)adj)[i] != 0u;
            int nz3 = ((const ull*)adj)[i] != 0ULL;
            if (i < 64 || i >= 1472) { lb[0] += nz0; lb[1] += nz1; lb[2] += nz2; lb[3] += nz3; }
            else                     { lc[0] += nz0; lc[1] += nz1; lc[2] += nz2; lc[3] += nz3; }
        }
#pragma unroll
        for (int s = 0; s < 4; s++) { atomicAdd(&s_bad[s], lb[s]); atomicAdd(&s_cnt[s], lc[s]); }
        __syncthreads();
        if (t == 0) {
            int f = 1;
            for (int s = 0; s < 4; s++)
                if (s_bad[s] == 0 && s_cnt[s] > 300 && s_cnt[s] < 1100) { f = 1 << s; break; }
            s_esz = f;
        }
        __syncthreads();
        int esz = s_esz;
        int w = b * 16 + (t >> 5);      // global warp id < 2304
        int wr = w / 48, ct = w % 48;   // row-word, col-tile
        int c0 = ct * 32, lane = t & 31;
        long rowbase = (long)(wr * 32 + lane) * NN + c0;
        unsigned myword = 0;
        if (esz == 1) {
            const uint4* p = (const uint4*)((const unsigned char*)adj + rowbase);
            uint4 v0 = p[0], v1 = p[1];
            unsigned u[8] = {v0.x, v0.y, v0.z, v0.w, v1.x, v1.y, v1.z, v1.w};
#pragma unroll
            for (int j = 0; j < 32; j++) {
                bool nz = ((u[j >> 2] >> ((j & 3) * 8)) & 255u) != 0u;
                unsigned bw = __ballot_sync(0xffffffffu, nz);
                if (lane == j) myword = bw;
            }
        } else if (esz == 4) {
            const uint4* p = (const uint4*)((const unsigned*)adj + rowbase);
#pragma unroll
            for (int q = 0; q < 8; q++) {
                uint4 v = p[q];
                unsigned nzm = 0;
                nzm |= (v.x != 0u) << 0; nzm |= (v.y != 0u) << 1;
                nzm |= (v.z != 0u) << 2; nzm |= (v.w != 0u) << 3;
#pragma unroll
                for (int j = 0; j < 4; j++) {
                    unsigned bw = __ballot_sync(0xffffffffu, (nzm >> j) & 1u);
                    if (lane == q * 4 + j) myword = bw;
                }
            }
        } else if (esz == 2) {
            const uint4* p = (const uint4*)((const unsigned short*)adj + rowbase);
#pragma unroll
            for (int q = 0; q < 4; q++) {
                uint4 v = p[q];
                unsigned u[4] = {v.x, v.y, v.z, v.w};
#pragma unroll
                for (int j = 0; j < 8; j++) {
                    bool nz = ((u[j >> 1] >> ((j & 1) * 16)) & 0xffffu) != 0u;
                    unsigned bw = __ballot_sync(0xffffffffu, nz);
                    if (lane == q * 8 + j) myword = bw;
                }
            }
        } else {
            const ull* p = (const ull*)adj + rowbase;
#pragma unroll
            for (int j = 0; j < 32; j++) {
                bool nz = p[j] != 0ULL;
                unsigned bw = __ballot_sync(0xffffffffu, nz);
                if (lane == j) myword = bw;
            }
        }
        g_bits[wr * NN + c0 + lane] = myword;
    } else if (b == 144) {
        {
            int i = t >> 3, d = t & 7;
            float s = 0.0f;
#pragma unroll
            for (int k = 0; k < 8; k++) s += nW_in[d * 8 + k];
            float v = tanhf(fmaf(obs[i], s, nb_in[d]));
            g_post_in[t] = v;
            if (out_post) out_post[t] = v;
        }
        __syncthreads();
        for (int e = t; e < II * NG; e += 512) {
            int r = e / NG, g = e % NG;
            float a = 0.0f;
#pragma unroll
            for (int k = 0; k < 8; k++) a = fmaf(Wih1[g * 17 + k], g_post_in[r * 8 + k], a);
            g_gi_pre1[e] = a;
        }
    } else if (b < 211) {
        int e = (b - 145) * 512 + t;    // < 33792
        int c = e / NG, g = e % NG;
        float a = fmaf(Wih1[g * 17 + 16], rew[0], bih1[g]);
        const float* p = post0 + (long)(II + c) * 8;
#pragma unroll
        for (int k = 0; k < 8; k++) a = fmaf(Wih1[g * 17 + 8 + k], p[k], a);
        g_gi_post1[e] = a;
    } else {
        int id = (b - 211) * 512 + t;   // < 106496
        int r, c;
        if (id < 8192) {
            r = id >> 7; int cc = id & 127; c = (cc < 64) ? cc : cc + HH;
        } else if (id < 8192 + 90112) {
            int e = id - 8192; r = II + (e >> 6); c = e & 63;
        } else {
            int e = id - 98304; r = II + HH + (e >> 7); int cc = e & 127; c = (cc < 64) ? cc : cc + HH;
        }
        long cell = (long)r * NN + c;
        const float* s = hid0 + cell * 8;
        float* d = out_hid + cell * 8;
#pragma unroll
        for (int k = 0; k < 8; k++) d[k] = s[k];
    }
}

// ---------------- folded GRU cell core ----------------
// accRZ[0..3]=r pairs, accRZ[4..7]=z pairs (already include gi sums);
// accN gh-only pairs; ginN gi pairs for n-gates.
__device__ __forceinline__ void gru_core(const ull accRZ[8], const ull accN[4], const ull ginN[4],
                                         const float h[8], float lr, bool m, float hn[8]) {
#pragma unroll
    for (int p = 0; p < 4; p++) {
        float r0, r1, z0, z1, gh0, gh1, gi0, gi1;
        up2(accRZ[p], r0, r1);     r0 = fsig(r0); r1 = fsig(r1);
        up2(accRZ[4 + p], z0, z1); z0 = fsig(z0); z1 = fsig(z1);
        up2(accN[p], gh0, gh1);
        up2(ginN[p], gi0, gi1);
        float n0 = ftanh(fmaf(r0, gh0, gi0));
        float n1 = ftanh(fmaf(r1, gh1, gi1));
        int d = 2 * p;
        float g0 = fmaf(z0, h[d] - n0, n0);
        float g1 = fmaf(z1, h[d + 1] - n1, n1);
        hn[d]     = m ? fmaf(lr, g0, h[d]) : h[d];
        hn[d + 1] = m ? fmaf(lr, g1, h[d + 1]) : h[d + 1];
    }
}

// ---------------- K2: stage 1 (64 rows x 1408 cols) ----------------
__global__ __launch_bounds__(256, 2) void k_stage1(
    const float* __restrict__ hid0, const float* __restrict__ Whh, const float* __restrict__ bhh,
    const float* __restrict__ lrp, float* __restrict__ out_hid) {
    __shared__ __align__(16) ull sw[96];
    __shared__ ull sb[12];
    __shared__ float red[4 * 64 * 8];
    int t = threadIdx.x;
    pack_whh(Whh, bhh, sw, sb, t, 256);
    __syncthreads();

    int r = t >> 2, cl = t & 3;
    int c = blockIdx.x * 4 + cl;
    float lr = lrp[0];
    long cell = (long)r * NN + (II + c);
    bool m = (g_bits[(r >> 5) * NN + (II + c)] >> (r & 31)) & 1u;
    const float4* hp = (const float4*)(hid0 + cell * 8);
    float4 ha = hp[0], hb4 = hp[1];
    float h[8] = {ha.x, ha.y, ha.z, ha.w, hb4.x, hb4.y, hb4.z, hb4.w};

    const float2* gp2 = (const float2*)(g_gi_pre1 + r * 24);
    const float2* gq2 = (const float2*)(g_gi_post1 + c * 24);
    ull hb[8];
#pragma unroll
    for (int k = 0; k < 8; k++) hb[k] = pk2(h[k], h[k]);
    ull accRZ[8], accN[4], ginN[4];
#pragma unroll
    for (int p = 0; p < 8; p++) {
        float2 a = gp2[p], bq = gq2[p];
        accRZ[p] = add2_(sb[p], pk2(a.x + bq.x, a.y + bq.y));
    }
#pragma unroll
    for (int p = 0; p < 4; p++) {
        float2 a = gp2[8 + p], bq = gq2[8 + p];
        accN[p] = sb[8 + p];
        ginN[p] = pk2(a.x + bq.x, a.y + bq.y);
    }
#pragma unroll
    for (int k = 0; k < 8; k++) {
#pragma unroll
        for (int p = 0; p < 8; p++) accRZ[p] = ffma2_(sw[p * 8 + k], hb[k], accRZ[p]);
#pragma unroll
        for (int p = 0; p < 4; p++) accN[p] = ffma2_(sw[(8 + p) * 8 + k], hb[k], accN[p]);
    }
    float hn[8];
    gru_core(accRZ, accN, ginN, h, lr, m, hn);

    if (out_hid) {
        float* op = out_hid + cell * 8;
#pragma unroll
        for (int d = 0; d < 8; d++) op[d] = hn[d];
    }
    const float* pre = g_post_in + r * 8;
#pragma unroll
    for (int d = 0; d < 8; d++) red[(cl * 64 + r) * 8 + d] = m ? hn[d] * pre[d] : 0.0f;
    __syncthreads();
    if (t < 32) {
        int cl2 = t >> 3, d = t & 7;
        float s = 0.0f;
        for (int k = 0; k < 64; k++) s += red[(cl2 * 64 + k) * 8 + d];
        g_csum1[(blockIdx.x * 4 + cl2) * 8 + d] = s;
    }
}

// ---------------- K3: mid ----------------
__global__ __launch_bounds__(256) void k_mid(
    const float* __restrict__ post0, const float* __restrict__ nW_hid, const float* __restrict__ nb_hid,
    const float* __restrict__ Wih2, const float* __restrict__ bih2,
    const float* __restrict__ Wih3, const float* __restrict__ bih3,
    const float* __restrict__ rew, float* __restrict__ out_post) {
    int id = blockIdx.x * 256 + threadIdx.x;
    if (id < HH) {
        int r = id;
        float ph[8];
#pragma unroll
        for (int d = 0; d < 8; d++) {
            float a = nb_hid[d];
#pragma unroll
            for (int k = 0; k < 8; k++) a = fmaf(g_csum1[r * 8 + k], nW_hid[d * 8 + k], a);
            ph[d] = tanhf(a);
        }
#pragma unroll
        for (int d = 0; d < 8; d++) {
            g_post_hid[r * 8 + d] = ph[d];
            if (out_post) out_post[(II + r) * 8 + d] = ph[d];
        }
        float rw = rew[0];
#pragma unroll
        for (int g = 0; g < 24; g++) {
            float a = 0.0f;
#pragma unroll
            for (int k = 0; k < 8; k++) a = fmaf(Wih2[g * 17 + k], ph[k], a);
            g_gi_pre2[r * 24 + g] = a;
            float b = fmaf(Wih3[g * 17 + 16], rw, bih3[g]);
#pragma unroll
            for (int k = 0; k < 8; k++) b = fmaf(Wih3[g * 17 + 8 + k], ph[k], b);
            g_gi_post3[r * 24 + g] = b;
        }
    } else if (id < HH + CC2) {
        int c = id - HH;
        float p[8];
        if (c < HH) {
#pragma unroll
            for (int d = 0; d < 8; d++) {
                float a = nb_hid[d];
#pragma unroll
                for (int k = 0; k < 8; k++) a = fmaf(g_csum1[c * 8 + k], nW_hid[d * 8 + k], a);
                p[d] = tanhf(a);
            }
        } else {
#pragma unroll
            for (int d = 0; d < 8; d++) p[d] = post0[(long)(II + c) * 8 + d];
        }
        float rw = rew[0];
#pragma unroll
        for (int g = 0; g < 24; g++) {
            float a = fmaf(Wih2[g * 17 + 16], rw, bih2[g]);
#pragma unroll
            for (int k = 0; k < 8; k++) a = fmaf(Wih2[g * 17 + 8 + k], p[k], a);
            g_gi_post2[c * 24 + g] = a;
        }
    }
}

// ---------------- K4: stage 2 (1408 rows x 1472 cols, 16-row tiles) ----------
__global__ __launch_bounds__(128, 4) void k_stage2(
    const float* __restrict__ hid0, const float* __restrict__ Whh, const float* __restrict__ bhh,
    const float* __restrict__ lrp, float* __restrict__ out_hid) {
    __shared__ __align__(16) ull sw[96];
    __shared__ ull sb[12];
    __shared__ ull s_gip2[16 * 12];
    __shared__ float s_pre[16 * 8];
    int t = threadIdx.x;
    int c = blockIdx.x * 128 + t;
    int yb = blockIdx.y;
    int r0 = yb * 16;
    pack_whh(Whh, bhh, sw, sb, t, 128);
    for (int e = t; e < 16 * 12; e += 128) {
        int row = e / 12, p = e % 12;
        float2 f = ((const float2*)(g_gi_pre2 + (r0 + row) * 24))[p];
        s_gip2[e] = pk2(f.x, f.y);
    }
    for (int e = t; e < 16 * 8; e += 128) s_pre[e] = g_post_hid[r0 * 8 + e];
    __syncthreads();
    if (c >= CC2) return;

    float lr = lrp[0];
    ull qrz[8], qngh[4], qngi[4];
    const float2* gq2 = (const float2*)(g_gi_post2 + c * 24);
#pragma unroll
    for (int p = 0; p < 8; p++) { float2 f = gq2[p]; qrz[p] = add2_(sb[p], pk2(f.x, f.y)); }
#pragma unroll
    for (int p = 0; p < 4; p++) {
        qngh[p] = sb[8 + p];
        float2 f = gq2[8 + p]; qngi[p] = pk2(f.x, f.y);
    }
    bool isOut = (c >= HH);
    float accO[8] = {0, 0, 0, 0, 0, 0, 0, 0};

    int gr = II + r0;
    unsigned mw = g_bits[(gr >> 5) * NN + (II + c)];
    int shift = gr & 31;
    const float* hrow = hid0 + ((long)gr * NN + (II + c)) * 8;
    float* orow = out_hid ? out_hid + ((long)gr * NN + (II + c)) * 8 : (float*)0;
    const long rstride = (long)NN * 8;

    float4 pa = ((const float4*)hrow)[0];
    float4 pb = ((const float4*)hrow)[1];

#pragma unroll 2
    for (int rr = 0; rr < 16; rr++) {
        float4 ha = pa, hb4 = pb;
        if (rr < 15) {
            const float4* np = (const float4*)(hrow + (rr + 1) * rstride);
            pa = np[0]; pb = np[1];
        }
        float h[8] = {ha.x, ha.y, ha.z, ha.w, hb4.x, hb4.y, hb4.z, hb4.w};
        ull hb[8];
#pragma unroll
        for (int k = 0; k < 8; k++) hb[k] = pk2(h[k], h[k]);

        ull accRZ[8], accN[4], ginN[4];
#pragma unroll
        for (int p = 0; p < 8; p++) accRZ[p] = add2_(qrz[p], s_gip2[rr * 12 + p]);
#pragma unroll
        for (int p = 0; p < 4; p++) {
            accN[p] = qngh[p];
            ginN[p] = add2_(qngi[p], s_gip2[rr * 12 + 8 + p]);
        }
#pragma unroll
        for (int k = 0; k < 8; k++) {
#pragma unroll
            for (int p = 0; p < 8; p++) accRZ[p] = ffma2_(sw[p * 8 + k], hb[k], accRZ[p]);
#pragma unroll
            for (int p = 0; p < 4; p++) accN[p] = ffma2_(sw[(8 + p) * 8 + k], hb[k], accN[p]);
        }
        bool m = (mw >> (shift + rr)) & 1u;
        float hn[8];
        gru_core(accRZ, accN, ginN, h, lr, m, hn);

        if (orow) {
            float* op = orow + rr * rstride;
#pragma unroll
            for (int d = 0; d < 8; d++) op[d] = hn[d];
        }
        if (isOut && m) {
#pragma unroll
            for (int d = 0; d < 8; d++) accO[d] = fmaf(hn[d], s_pre[rr * 8 + d], accO[d]);
        }
    }
    if (isOut) {
        float* p = g_csum2p + ((long)yb * 64 + (c - HH)) * 8;
#pragma unroll
        for (int d = 0; d < 8; d++) p[d] = accO[d];
    }
}

// ---------------- K5: stage 3 + post_out + argmax ----------------
__global__ __launch_bounds__(128, 4) void k_stage3(
    const float* __restrict__ hid0, const float* __restrict__ Whh, const float* __restrict__ bhh,
    const float* __restrict__ lrp, const float* __restrict__ nW_out, const float* __restrict__ nb_out,
    const float* __restrict__ Wih3,
    float* __restrict__ out_hid, float* __restrict__ out_post, float* __restrict__ out_act) {
    int t = threadIdx.x, x = blockIdx.x, o = blockIdx.y;
    if (x == 11) {
        if (o) return;
        __shared__ float scs[64 * 8];
        __shared__ float spo[64];
        for (int e = t; e < 512; e += 128) {
            int oo = e >> 3, d = e & 7;
            float s = 0.0f;
            for (int y = 0; y < YB2; y++) s += g_csum2p[((long)y * 64 + oo) * 8 + d];
            scs[e] = s;
        }
        __syncthreads();
        for (int e = t; e < 512; e += 128) {
            int oo = e >> 3, d = e & 7;
            float a = nb_out[d];
#pragma unroll
            for (int k = 0; k < 8; k++) a = fmaf(scs[oo * 8 + k], nW_out[d * 8 + k], a);
            float v = eigen_tanh(a);
            if (out_post) out_post[(II + HH) * 8 + e] = v;
            if (d == 0) spo[oo] = v;
        }
        __syncthreads();
        if (t == 0) {
            float best = spo[0];
            for (int oo = 1; oo < 64; oo++) if (spo[oo] > best) best = spo[oo];
            int bi = 0;
            for (int oo = 0; oo < 64; oo++) if (spo[oo] >= best - 1.2e-7f) { bi = oo; break; }
            out_act[0] = (float)bi;
        }
        return;
    }

    __shared__ __align__(16) ull sw[96];
    __shared__ ull sb[12];
    __shared__ float scs8[8], spo8[8], sgp[24];
    pack_whh(Whh, bhh, sw, sb, t, 128);
    if (t < 8) {
        float s = 0.0f;
        for (int y = 0; y < YB2; y++) s += g_csum2p[((long)y * 64 + o) * 8 + t];
        scs8[t] = s;
    }
    __syncthreads();
    if (t < 8) {
        float a = nb_out[t];
#pragma unroll
        for (int k = 0; k < 8; k++) a = fmaf(scs8[k], nW_out[t * 8 + k], a);
        spo8[t] = eigen_tanh(a);
    }
    __syncthreads();
    if (t < 24) {
        float a = 0.0f;
#pragma unroll
        for (int k = 0; k < 8; k++) a = fmaf(Wih3[t * 17 + k], spo8[k], a);
        sgp[t] = a;
    }
    __syncthreads();

    int c = x * 128 + t;
    float lr = lrp[0];
    int R = II + HH + o;
    long cell = (long)R * NN + (II + c);
    bool m = (g_bits[(R >> 5) * NN + (II + c)] >> (R & 31)) & 1u;
    const float4* hp = (const float4*)(hid0 + cell * 8);
    float4 ha = hp[0], hb4 = hp[1];
    float h[8] = {ha.x, ha.y, ha.z, ha.w, hb4.x, hb4.y, hb4.z, hb4.w};

    const float2* gq2 = (const float2*)(g_gi_post3 + c * 24);
    ull hb[8];
#pragma unroll
    for (int k = 0; k < 8; k++) hb[k] = pk2(h[k], h[k]);
    ull accRZ[8], accN[4], ginN[4];
#pragma unroll
    for (int p = 0; p < 8; p++) {
        float2 f = gq2[p];
        accRZ[p] = add2_(sb[p], pk2(f.x + sgp[2 * p], f.y + sgp[2 * p + 1]));
    }
#pragma unroll
    for (int p = 0; p < 4; p++) {
        float2 f = gq2[8 + p];
        accN[p] = sb[8 + p];
        ginN[p] = pk2(f.x + sgp[16 + 2 * p], f.y + sgp[17 + 2 * p]);
    }
#pragma unroll
    for (int k = 0; k < 8; k++) {
#pragma unroll
        for (int p = 0; p < 8; p++) accRZ[p] = ffma2_(sw[p * 8 + k], hb[k], accRZ[p]);
#pragma unroll
        for (int p = 0; p < 4; p++) accN[p] = ffma2_(sw[(8 + p) * 8 + k], hb[k], accN[p]);
    }
    float hn[8];
    gru_core(accRZ, accN, ginN, h, lr, m, hn);

    if (out_hid) {
        float* op = out_hid + cell * 8;
#pragma unroll
        for (int d = 0; d < 8; d++) op[d] = hn[d];
    }
}

// ---------------- launch ----------------
extern "C" void kernel_launch(void* const* d_in, const int* in_sizes, int n_in,
                              void* d_out, int out_size) {
    const float* obs   = (const float*)d_in[0];
    const float* rew   = (const float*)d_in[1];
    const float* lrp   = (const float*)d_in[2];
    const float* post0 = (const float*)d_in[3];
    const float* hid0  = (const float*)d_in[4];
    const void*  adj   = d_in[5];
    const float* nW_in  = (const float*)d_in[6];
    const float* nb_in  = (const float*)d_in[7];
    const float* nW_hid = (const float*)d_in[8];
    const float* nb_hid = (const float*)d_in[9];
    const float* nW_out = (const float*)d_in[10];
    const float* nb_out = (const float*)d_in[11];
    const float* Wih1 = (const float*)d_in[12];
    const float* Whh1 = (const float*)d_in[13];
    const float* bih1 = (const float*)d_in[14];
    const float* bhh1 = (const float*)d_in[15];
    const float* Wih2 = (const float*)d_in[16];
    const float* Whh2 = (const float*)d_in[17];
    const float* bih2 = (const float*)d_in[18];
    const float* bhh2 = (const float*)d_in[19];
    const float* Wih3 = (const float*)d_in[20];
    const float* Whh3 = (const float*)d_in[21];
    const float* bih3 = (const float*)d_in[22];
    const float* bhh3 = (const float*)d_in[23];

    const long FULL = 1L + (long)NN * DD + (long)NN * NN * DD;
    float* out      = (float*)d_out;
    float* out_act  = out;
    float* out_post = nullptr;
    float* out_hid  = nullptr;
    if ((long)out_size >= FULL) {
        out_post = out + 1;
        out_hid  = out + 1 + (long)NN * DD;
    } else if ((long)out_size >= 1 + (long)NN * DD) {
        out_post = out + 1;
    }

    int nblk = 211 + (out_hid ? 208 : 0);
    k_setup<<<nblk, 512>>>(adj, obs, nW_in, nb_in, Wih1, bih1, post0, rew, hid0,
                           out_post, out_hid);
    k_stage1<<<352, 256>>>(hid0, Whh1, bhh1, lrp, out_hid);
    k_mid<<<12, 256>>>(post0, nW_hid, nb_hid, Wih2, bih2, Wih3, bih3, rew, out_post);
    dim3 g2(12, YB2);
    k_stage2<<<g2, 128>>>(hid0, Whh2, bhh2, lrp, out_hid);
    dim3 g3(12, 64);
    k_stage3<<<g3, 128>>>(hid0, Whh3, bhh3, lrp, nW_out, nb_out, Wih3,
                          out_hid, out_post, out_act);
}

// round 14
// speedup vs baseline: 1.1061x; 1.1061x over previous
#include <cuda_runtime.h>
#include <math.h>

#define II 64
#define HH 1408
#define OO 64
#define NN 1536
#define DD 8
#define NG 24
#define CC2 (HH + OO)   // 1472
#define YB2 88          // stage2 y-blocks (16 rows each)

typedef unsigned long long ull;

// ---------------- device scratch ----------------
__device__ float g_post_in[II * DD];
__device__ float g_post_hid[HH * DD];
__device__ float g_gi_pre1[II * NG];
__device__ float g_gi_post1[HH * NG];
__device__ float g_gi_pre2[HH * NG];
__device__ float g_gi_post2[CC2 * NG];
__device__ float g_gi_post3[HH * NG];
__device__ float g_csum1[HH * DD];
__device__ float g_csum2p[YB2 * 64 * DD];    // stage2 partials [yb][o][d]
__device__ unsigned g_bits[48 * NN];         // mask word[r/32][col], bit r%32

// ---------------- packed f32x2 helpers ----------------
__device__ __forceinline__ ull pk2(float lo, float hi) {
    ull r;
    asm("mov.b64 %0, {%1, %2};" : "=l"(r) : "r"(__float_as_uint(lo)), "r"(__float_as_uint(hi)));
    return r;
}
__device__ __forceinline__ void up2(ull v, float& lo, float& hi) {
    unsigned a, b;
    asm("mov.b64 {%0, %1}, %2;" : "=r"(a), "=r"(b) : "l"(v));
    lo = __uint_as_float(a); hi = __uint_as_float(b);
}
__device__ __forceinline__ ull ffma2_(ull a, ull b, ull c) {
    ull r;
    asm("fma.rn.f32x2 %0, %1, %2, %3;" : "=l"(r) : "l"(a), "l"(b), "l"(c));
    return r;
}
__device__ __forceinline__ ull add2_(ull a, ull b) {
    ull r;
    asm("add.rn.f32x2 %0, %1, %2;" : "=l"(r) : "l"(a), "l"(b));
    return r;
}

// ---------------- fast activations ----------------
__device__ __forceinline__ float ftanh(float x) {
    float y;
    asm("tanh.approx.f32 %0, %1;" : "=f"(y) : "f"(x));
    return y;
}
__device__ __forceinline__ float fsig(float x) {
    return fmaf(0.5f, ftanh(0.5f * x), 0.5f);
}

// Eigen/XLA-style f32 rational tanh (reference-matching saturation)
__device__ __forceinline__ float eigen_tanh(float x) {
    const float mx = 7.90531110763549805f;
    float xc = fminf(fmaxf(x, -mx), mx);
    float x2 = xc * xc;
    float p = -2.76076847742355e-16f;
    p = fmaf(x2, p, 2.00018790482477e-13f);
    p = fmaf(x2, p, -8.60467152213735e-11f);
    p = fmaf(x2, p, 5.12229709037114e-08f);
    p = fmaf(x2, p, 1.48572235717979e-05f);
    p = fmaf(x2, p, 6.37261928875436e-04f);
    p = fmaf(x2, p, 4.89352455891786e-03f);
    p = xc * p;
    float q = 1.19825839466702e-06f;
    q = fmaf(x2, q, 1.18534705686654e-04f);
    q = fmaf(x2, q, 2.26843463243900e-03f);
    q = fmaf(x2, q, 4.89352518554385e-03f);
    float r = p / q;
    if (fabsf(x) < 0.0004f) r = x;
    return r;
}

// ---------------- Whh pack: sw[p*8+k] = (W[2p][k], W[2p+1][k]), sb pairs ----
__device__ __forceinline__ void pack_whh(const float* __restrict__ W, const float* __restrict__ b,
                                         ull* sw, ull* sb, int t, int nt) {
    for (int e = t; e < 96; e += nt) {
        int p = e >> 3, k = e & 7;
        sw[e] = pk2(W[(2 * p) * 8 + k], W[(2 * p + 1) * 8 + k]);
    }
    for (int e = t; e < 12; e += nt) sb[e] = pk2(b[2 * e], b[2 * e + 1]);
}

// ---------------- folded GRU core on packed h pairs ----------------
// accRZ[0..3]=r pairs, accRZ[4..7]=z pairs (include all gi);
// accN = gh-only pairs; ginN = gi pairs for n-gates; hb[k]=(h[k],h[k]).
__device__ __forceinline__ void gru_core(const ull accRZ[8], const ull accN[4], const ull ginN[4],
                                         const ull hb[8], float lr, bool m, float hn[8]) {
#pragma unroll
    for (int p = 0; p < 4; p++) {
        float r0, r1, z0, z1, gh0, gh1, gi0, gi1, h0, h1, d0, d1;
        up2(accRZ[p], r0, r1);     r0 = fsig(r0); r1 = fsig(r1);
        up2(accRZ[4 + p], z0, z1); z0 = fsig(z0); z1 = fsig(z1);
        up2(accN[p], gh0, gh1);
        up2(ginN[p], gi0, gi1);
        float n0 = ftanh(fmaf(r0, gh0, gi0));
        float n1 = ftanh(fmaf(r1, gh1, gi1));
        up2(hb[2 * p], h0, d0);
        up2(hb[2 * p + 1], h1, d1);
        float g0 = fmaf(z0, h0 - n0, n0);
        float g1 = fmaf(z1, h1 - n1, n1);
        hn[2 * p]     = m ? fmaf(lr, g0, h0) : h0;
        hn[2 * p + 1] = m ? fmaf(lr, g1, h1) : h1;
    }
}

// ---------------- K1: setup mega-kernel ----------------
__global__ __launch_bounds__(512) void k_setup(
    const void* __restrict__ adj, const float* __restrict__ obs,
    const float* __restrict__ nW_in, const float* __restrict__ nb_in,
    const float* __restrict__ Wih1, const float* __restrict__ bih1,
    const float* __restrict__ post0, const float* __restrict__ rew,
    const float* __restrict__ hid0,
    float* __restrict__ out_post, float* __restrict__ out_hid) {
    int b = blockIdx.x, t = threadIdx.x;
    if (b < 144) {
        __shared__ int s_bad[4], s_cnt[4], s_esz;
        if (t < 4) { s_bad[t] = 0; s_cnt[t] = 0; }
        __syncthreads();
        int lb[4] = {0, 0, 0, 0}, lc[4] = {0, 0, 0, 0};
        for (int i = t; i < 1600; i += 512) {
            int nz0 = ((const unsigned char*)adj)[i] != 0;
            int nz1 = ((const unsigned short*)adj)[i] != 0;
            int nz2 = ((const unsigned int*)adj)[i] != 0u;
            int nz3 = ((const ull*)adj)[i] != 0ULL;
            if (i < 64 || i >= 1472) { lb[0] += nz0; lb[1] += nz1; lb[2] += nz2; lb[3] += nz3; }
            else                     { lc[0] += nz0; lc[1] += nz1; lc[2] += nz2; lc[3] += nz3; }
        }
#pragma unroll
        for (int s = 0; s < 4; s++) { atomicAdd(&s_bad[s], lb[s]); atomicAdd(&s_cnt[s], lc[s]); }
        __syncthreads();
        if (t == 0) {
            int f = 1;
            for (int s = 0; s < 4; s++)
                if (s_bad[s] == 0 && s_cnt[s] > 300 && s_cnt[s] < 1100) { f = 1 << s; break; }
            s_esz = f;
        }
        __syncthreads();
        int esz = s_esz;
        int w = b * 16 + (t >> 5);      // global warp id < 2304
        int wr = w / 48, ct = w % 48;   // row-word, col-tile
        int c0 = ct * 32, lane = t & 31;
        long rowbase = (long)(wr * 32 + lane) * NN + c0;
        unsigned myword = 0;
        if (esz == 1) {
            const uint4* p = (const uint4*)((const unsigned char*)adj + rowbase);
            uint4 v0 = p[0], v1 = p[1];
            unsigned u[8] = {v0.x, v0.y, v0.z, v0.w, v1.x, v1.y, v1.z, v1.w};
#pragma unroll
            for (int j = 0; j < 32; j++) {
                bool nz = ((u[j >> 2] >> ((j & 3) * 8)) & 255u) != 0u;
                unsigned bw = __ballot_sync(0xffffffffu, nz);
                if (lane == j) myword = bw;
            }
        } else if (esz == 4) {
            const uint4* p = (const uint4*)((const unsigned*)adj + rowbase);
#pragma unroll
            for (int q = 0; q < 8; q++) {
                uint4 v = p[q];
                unsigned nzm = 0;
                nzm |= (v.x != 0u) << 0; nzm |= (v.y != 0u) << 1;
                nzm |= (v.z != 0u) << 2; nzm |= (v.w != 0u) << 3;
#pragma unroll
                for (int j = 0; j < 4; j++) {
                    unsigned bw = __ballot_sync(0xffffffffu, (nzm >> j) & 1u);
                    if (lane == q * 4 + j) myword = bw;
                }
            }
        } else if (esz == 2) {
            const uint4* p = (const uint4*)((const unsigned short*)adj + rowbase);
#pragma unroll
            for (int q = 0; q < 4; q++) {
                uint4 v = p[q];
                unsigned u[4] = {v.x, v.y, v.z, v.w};
#pragma unroll
                for (int j = 0; j < 8; j++) {
                    bool nz = ((u[j >> 1] >> ((j & 1) * 16)) & 0xffffu) != 0u;
                    unsigned bw = __ballot_sync(0xffffffffu, nz);
                    if (lane == q * 8 + j) myword = bw;
                }
            }
        } else {
            const ull* p = (const ull*)adj + rowbase;
#pragma unroll
            for (int j = 0; j < 32; j++) {
                bool nz = p[j] != 0ULL;
                unsigned bw = __ballot_sync(0xffffffffu, nz);
                if (lane == j) myword = bw;
            }
        }
        g_bits[wr * NN + c0 + lane] = myword;
    } else if (b == 144) {
        {
            int i = t >> 3, d = t & 7;
            float s = 0.0f;
#pragma unroll
            for (int k = 0; k < 8; k++) s += nW_in[d * 8 + k];
            float v = tanhf(fmaf(obs[i], s, nb_in[d]));
            g_post_in[t] = v;
            if (out_post) out_post[t] = v;
        }
        __syncthreads();
        for (int e = t; e < II * NG; e += 512) {
            int r = e / NG, g = e % NG;
            float a = 0.0f;
#pragma unroll
            for (int k = 0; k < 8; k++) a = fmaf(Wih1[g * 17 + k], g_post_in[r * 8 + k], a);
            g_gi_pre1[e] = a;
        }
    } else if (b < 211) {
        int e = (b - 145) * 512 + t;    // < 33792
        int c = e / NG, g = e % NG;
        float a = fmaf(Wih1[g * 17 + 16], rew[0], bih1[g]);
        const float* p = post0 + (long)(II + c) * 8;
#pragma unroll
        for (int k = 0; k < 8; k++) a = fmaf(Wih1[g * 17 + 8 + k], p[k], a);
        g_gi_post1[e] = a;
    } else {
        int id = (b - 211) * 512 + t;   // < 106496
        int r, c;
        if (id < 8192) {
            r = id >> 7; int cc = id & 127; c = (cc < 64) ? cc : cc + HH;
        } else if (id < 8192 + 90112) {
            int e = id - 8192; r = II + (e >> 6); c = e & 63;
        } else {
            int e = id - 98304; r = II + HH + (e >> 7); int cc = e & 127; c = (cc < 64) ? cc : cc + HH;
        }
        long cell = (long)r * NN + c;
        const float* s = hid0 + cell * 8;
        float* d = out_hid + cell * 8;
#pragma unroll
        for (int k = 0; k < 8; k++) d[k] = s[k];
    }
}

// ---------------- K2: stage 1 (64 rows x 1408 cols) ----------------
__global__ __launch_bounds__(256, 2) void k_stage1(
    const float* __restrict__ hid0, const float* __restrict__ Whh, const float* __restrict__ bhh,
    const float* __restrict__ lrp, float* __restrict__ out_hid) {
    __shared__ __align__(16) ull sw[96];
    __shared__ ull sb[12];
    __shared__ float red[4 * 64 * 8];
    int t = threadIdx.x;
    pack_whh(Whh, bhh, sw, sb, t, 256);
    __syncthreads();

    int r = t >> 2, cl = t & 3;
    int c = blockIdx.x * 4 + cl;
    float lr = lrp[0];
    long cell = (long)r * NN + (II + c);
    bool m = (g_bits[(r >> 5) * NN + (II + c)] >> (r & 31)) & 1u;
    const float4* hp = (const float4*)(hid0 + cell * 8);
    float4 ha = hp[0], hb4 = hp[1];
    ull hb[8];
    hb[0] = pk2(ha.x, ha.x); hb[1] = pk2(ha.y, ha.y);
    hb[2] = pk2(ha.z, ha.z); hb[3] = pk2(ha.w, ha.w);
    hb[4] = pk2(hb4.x, hb4.x); hb[5] = pk2(hb4.y, hb4.y);
    hb[6] = pk2(hb4.z, hb4.z); hb[7] = pk2(hb4.w, hb4.w);

    const float2* gp2 = (const float2*)(g_gi_pre1 + r * 24);
    const float2* gq2 = (const float2*)(g_gi_post1 + c * 24);
    ull accRZ[8], accN[4], ginN[4];
#pragma unroll
    for (int p = 0; p < 8; p++) {
        float2 a = gp2[p], bq = gq2[p];
        accRZ[p] = add2_(sb[p], pk2(a.x + bq.x, a.y + bq.y));
    }
#pragma unroll
    for (int p = 0; p < 4; p++) {
        float2 a = gp2[8 + p], bq = gq2[8 + p];
        accN[p] = sb[8 + p];
        ginN[p] = pk2(a.x + bq.x, a.y + bq.y);
    }
#pragma unroll
    for (int k = 0; k < 8; k++) {
#pragma unroll
        for (int p = 0; p < 8; p++) accRZ[p] = ffma2_(sw[p * 8 + k], hb[k], accRZ[p]);
#pragma unroll
        for (int p = 0; p < 4; p++) accN[p] = ffma2_(sw[(8 + p) * 8 + k], hb[k], accN[p]);
    }
    float hn[8];
    gru_core(accRZ, accN, ginN, hb, lr, m, hn);

    if (out_hid) {
        float* op = out_hid + cell * 8;
#pragma unroll
        for (int d = 0; d < 8; d++) op[d] = hn[d];
    }
    const float* pre = g_post_in + r * 8;
#pragma unroll
    for (int d = 0; d < 8; d++) red[(cl * 64 + r) * 8 + d] = m ? hn[d] * pre[d] : 0.0f;
    __syncthreads();
    if (t < 32) {
        int cl2 = t >> 3, d = t & 7;
        float s = 0.0f;
        for (int k = 0; k < 64; k++) s += red[(cl2 * 64 + k) * 8 + d];
        g_csum1[(blockIdx.x * 4 + cl2) * 8 + d] = s;
    }
}

// ---------------- K3: mid ----------------
__global__ __launch_bounds__(256) void k_mid(
    const float* __restrict__ post0, const float* __restrict__ nW_hid, const float* __restrict__ nb_hid,
    const float* __restrict__ Wih2, const float* __restrict__ bih2,
    const float* __restrict__ Wih3, const float* __restrict__ bih3,
    const float* __restrict__ rew, float* __restrict__ out_post) {
    int id = blockIdx.x * 256 + threadIdx.x;
    if (id < HH) {
        int r = id;
        float ph[8];
#pragma unroll
        for (int d = 0; d < 8; d++) {
            float a = nb_hid[d];
#pragma unroll
            for (int k = 0; k < 8; k++) a = fmaf(g_csum1[r * 8 + k], nW_hid[d * 8 + k], a);
            ph[d] = tanhf(a);
        }
#pragma unroll
        for (int d = 0; d < 8; d++) {
            g_post_hid[r * 8 + d] = ph[d];
            if (out_post) out_post[(II + r) * 8 + d] = ph[d];
        }
        float rw = rew[0];
#pragma unroll
        for (int g = 0; g < 24; g++) {
            float a = 0.0f;
#pragma unroll
            for (int k = 0; k < 8; k++) a = fmaf(Wih2[g * 17 + k], ph[k], a);
            g_gi_pre2[r * 24 + g] = a;
            float b = fmaf(Wih3[g * 17 + 16], rw, bih3[g]);
#pragma unroll
            for (int k = 0; k < 8; k++) b = fmaf(Wih3[g * 17 + 8 + k], ph[k], b);
            g_gi_post3[r * 24 + g] = b;
        }
    } else if (id < HH + CC2) {
        int c = id - HH;
        float p[8];
        if (c < HH) {
#pragma unroll
            for (int d = 0; d < 8; d++) {
                float a = nb_hid[d];
#pragma unroll
                for (int k = 0; k < 8; k++) a = fmaf(g_csum1[c * 8 + k], nW_hid[d * 8 + k], a);
                p[d] = tanhf(a);
            }
        } else {
#pragma unroll
            for (int d = 0; d < 8; d++) p[d] = post0[(long)(II + c) * 8 + d];
        }
        float rw = rew[0];
#pragma unroll
        for (int g = 0; g < 24; g++) {
            float a = fmaf(Wih2[g * 17 + 16], rw, bih2[g]);
#pragma unroll
            for (int k = 0; k < 8; k++) a = fmaf(Wih2[g * 17 + 8 + k], p[k], a);
            g_gi_post2[c * 24 + g] = a;
        }
    }
}

// ---------------- K4: stage 2 (1408 rows x 1472 cols, 16-row tiles) ----------
__global__ __launch_bounds__(128, 3) void k_stage2(
    const float* __restrict__ hid0, const float* __restrict__ Whh, const float* __restrict__ bhh,
    const float* __restrict__ lrp, float* __restrict__ out_hid) {
    __shared__ __align__(16) ull sw[96];
    __shared__ ull sb[12];
    __shared__ ull s_gip2[16 * 12];
    __shared__ float s_pre[16 * 8];
    int t = threadIdx.x;
    int c = blockIdx.x * 128 + t;
    int yb = blockIdx.y;
    int r0 = yb * 16;
    pack_whh(Whh, bhh, sw, sb, t, 128);
    for (int e = t; e < 16 * 12; e += 128) {
        int row = e / 12, p = e % 12;
        float2 f = ((const float2*)(g_gi_pre2 + (r0 + row) * 24))[p];
        s_gip2[e] = pk2(f.x, f.y);
    }
    for (int e = t; e < 16 * 8; e += 128) s_pre[e] = g_post_hid[r0 * 8 + e];
    __syncthreads();
    if (c >= CC2) return;

    float lr = lrp[0];
    ull qrz[8], qngi[4];
    const float2* gq2 = (const float2*)(g_gi_post2 + c * 24);
#pragma unroll
    for (int p = 0; p < 8; p++) { float2 f = gq2[p]; qrz[p] = add2_(sb[p], pk2(f.x, f.y)); }
#pragma unroll
    for (int p = 0; p < 4; p++) { float2 f = gq2[8 + p]; qngi[p] = pk2(f.x, f.y); }
    bool isOut = (c >= HH);
    float accO[8] = {0, 0, 0, 0, 0, 0, 0, 0};

    int gr = II + r0;
    unsigned mw = g_bits[(gr >> 5) * NN + (II + c)];
    int shift = gr & 31;
    const float* hrow = hid0 + ((long)gr * NN + (II + c)) * 8;
    float* orow = out_hid ? out_hid + ((long)gr * NN + (II + c)) * 8 : (float*)0;
    const long rstride = (long)NN * 8;

    float4 pa = ((const float4*)hrow)[0];
    float4 pb = ((const float4*)hrow)[1];

#pragma unroll 2
    for (int rr = 0; rr < 16; rr++) {
        ull hb[8];
        hb[0] = pk2(pa.x, pa.x); hb[1] = pk2(pa.y, pa.y);
        hb[2] = pk2(pa.z, pa.z); hb[3] = pk2(pa.w, pa.w);
        hb[4] = pk2(pb.x, pb.x); hb[5] = pk2(pb.y, pb.y);
        hb[6] = pk2(pb.z, pb.z); hb[7] = pk2(pb.w, pb.w);
        if (rr < 15) {
            const float4* np = (const float4*)(hrow + (rr + 1) * rstride);
            pa = np[0]; pb = np[1];
        }

        ull accRZ[8], accN[4], ginN[4];
#pragma unroll
        for (int p = 0; p < 8; p++) accRZ[p] = add2_(qrz[p], s_gip2[rr * 12 + p]);
#pragma unroll
        for (int p = 0; p < 4; p++) {
            accN[p] = sb[8 + p];
            ginN[p] = add2_(qngi[p], s_gip2[rr * 12 + 8 + p]);
        }
#pragma unroll
        for (int k = 0; k < 8; k++) {
#pragma unroll
            for (int p = 0; p < 8; p++) accRZ[p] = ffma2_(sw[p * 8 + k], hb[k], accRZ[p]);
#pragma unroll
            for (int p = 0; p < 4; p++) accN[p] = ffma2_(sw[(8 + p) * 8 + k], hb[k], accN[p]);
        }
        bool m = (mw >> (shift + rr)) & 1u;
        float hn[8];
        gru_core(accRZ, accN, ginN, hb, lr, m, hn);

        if (orow) {
            float* op = orow + rr * rstride;
#pragma unroll
            for (int d = 0; d < 8; d++) op[d] = hn[d];
        }
        if (isOut && m) {
#pragma unroll
            for (int d = 0; d < 8; d++) accO[d] = fmaf(hn[d], s_pre[rr * 8 + d], accO[d]);
        }
    }
    if (isOut) {
        float* p = g_csum2p + ((long)yb * 64 + (c - HH)) * 8;
#pragma unroll
        for (int d = 0; d < 8; d++) p[d] = accO[d];
    }
}

// ---------------- K5: stage 3 + post_out + argmax ----------------
__global__ __launch_bounds__(128, 3) void k_stage3(
    const float* __restrict__ hid0, const float* __restrict__ Whh, const float* __restrict__ bhh,
    const float* __restrict__ lrp, const float* __restrict__ nW_out, const float* __restrict__ nb_out,
    const float* __restrict__ Wih3,
    float* __restrict__ out_hid, float* __restrict__ out_post, float* __restrict__ out_act) {
    int t = threadIdx.x, x = blockIdx.x, o = blockIdx.y;
    if (x == 11) {
        if (o) return;
        __shared__ float scs[64 * 8];
        __shared__ float spo[64];
        for (int e = t; e < 512; e += 128) {
            int oo = e >> 3, d = e & 7;
            float s = 0.0f;
            for (int y = 0; y < YB2; y++) s += g_csum2p[((long)y * 64 + oo) * 8 + d];
            scs[e] = s;
        }
        __syncthreads();
        for (int e = t; e < 512; e += 128) {
            int oo = e >> 3, d = e & 7;
            float a = nb_out[d];
#pragma unroll
            for (int k = 0; k < 8; k++) a = fmaf(scs[oo * 8 + k], nW_out[d * 8 + k], a);
            float v = eigen_tanh(a);
            if (out_post) out_post[(II + HH) * 8 + e] = v;
            if (d == 0) spo[oo] = v;
        }
        __syncthreads();
        if (t == 0) {
            float best = spo[0];
            for (int oo = 1; oo < 64; oo++) if (spo[oo] > best) best = spo[oo];
            int bi = 0;
            for (int oo = 0; oo < 64; oo++) if (spo[oo] >= best - 1.2e-7f) { bi = oo; break; }
            out_act[0] = (float)bi;
        }
        return;
    }

    __shared__ __align__(16) ull sw[96];
    __shared__ ull sb[12];
    __shared__ float scs8[8], spo8[8], sgp[24];
    pack_whh(Whh, bhh, sw, sb, t, 128);
    if (t < 8) {
        float s = 0.0f;
        for (int y = 0; y < YB2; y++) s += g_csum2p[((long)y * 64 + o) * 8 + t];
        scs8[t] = s;
    }
    __syncthreads();
    if (t < 8) {
        float a = nb_out[t];
#pragma unroll
        for (int k = 0; k < 8; k++) a = fmaf(scs8[k], nW_out[t * 8 + k], a);
        spo8[t] = eigen_tanh(a);
    }
    __syncthreads();
    if (t < 24) {
        float a = 0.0f;
#pragma unroll
        for (int k = 0; k < 8; k++) a = fmaf(Wih3[t * 17 + k], spo8[k], a);
        sgp[t] = a;
    }
    __syncthreads();

    int c = x * 128 + t;
    float lr = lrp[0];
    int R = II + HH + o;
    long cell = (long)R * NN + (II + c);
    bool m = (g_bits[(R >> 5) * NN + (II + c)] >> (R & 31)) & 1u;
    const float4* hp = (const float4*)(hid0 + cell * 8);
    float4 ha = hp[0], hb4 = hp[1];
    ull hb[8];
    hb[0] = pk2(ha.x, ha.x); hb[1] = pk2(ha.y, ha.y);
    hb[2] = pk2(ha.z, ha.z); hb[3] = pk2(ha.w, ha.w);
    hb[4] = pk2(hb4.x, hb4.x); hb[5] = pk2(hb4.y, hb4.y);
    hb[6] = pk2(hb4.z, hb4.z); hb[7] = pk2(hb4.w, hb4.w);

    const float2* gq2 = (const float2*)(g_gi_post3 + c * 24);
    ull accRZ[8], accN[4], ginN[4];
#pragma unroll
    for (int p = 0; p < 8; p++) {
        float2 f = gq2[p];
        accRZ[p] = add2_(sb[p], pk2(f.x + sgp[2 * p], f.y + sgp[2 * p + 1]));
    }
#pragma unroll
    for (int p = 0; p < 4; p++) {
        float2 f = gq2[8 + p];
        accN[p] = sb[8 + p];
        ginN[p] = pk2(f.x + sgp[16 + 2 * p], f.y + sgp[17 + 2 * p]);
    }
#pragma unroll
    for (int k = 0; k < 8; k++) {
#pragma unroll
        for (int p = 0; p < 8; p++) accRZ[p] = ffma2_(sw[p * 8 + k], hb[k], accRZ[p]);
#pragma unroll
        for (int p = 0; p < 4; p++) accN[p] = ffma2_(sw[(8 + p) * 8 + k], hb[k], accN[p]);
    }
    float hn[8];
    gru_core(accRZ, accN, ginN, hb, lr, m, hn);

    if (out_hid) {
        float* op = out_hid + cell * 8;
#pragma unroll
        for (int d = 0; d < 8; d++) op[d] = hn[d];
    }
}

// ---------------- launch ----------------
extern "C" void kernel_launch(void* const* d_in, const int* in_sizes, int n_in,
                              void* d_out, int out_size) {
    const float* obs   = (const float*)d_in[0];
    const float* rew   = (const float*)d_in[1];
    const float* lrp   = (const float*)d_in[2];
    const float* post0 = (const float*)d_in[3];
    const float* hid0  = (const float*)d_in[4];
    const void*  adj   = d_in[5];
    const float* nW_in  = (const float*)d_in[6];
    const float* nb_in  = (const float*)d_in[7];
    const float* nW_hid = (const float*)d_in[8];
    const float* nb_hid = (const float*)d_in[9];
    const float* nW_out = (const float*)d_in[10];
    const float* nb_out = (const float*)d_in[11];
    const float* Wih1 = (const float*)d_in[12];
    const float* Whh1 = (const float*)d_in[13];
    const float* bih1 = (const float*)d_in[14];
    const float* bhh1 = (const float*)d_in[15];
    const float* Wih2 = (const float*)d_in[16];
    const float* Whh2 = (const float*)d_in[17];
    const float* bih2 = (const float*)d_in[18];
    const float* bhh2 = (const float*)d_in[19];
    const float* Wih3 = (const float*)d_in[20];
    const float* Whh3 = (const float*)d_in[21];
    const float* bih3 = (const float*)d_in[22];
    const float* bhh3 = (const float*)d_in[23];

    const long FULL = 1L + (long)NN * DD + (long)NN * NN * DD;
    float* out      = (float*)d_out;
    float* out_act  = out;
    float* out_post = nullptr;
    float* out_hid  = nullptr;
    if ((long)out_size >= FULL) {
        out_post = out + 1;
        out_hid  = out + 1 + (long)NN * DD;
    } else if ((long)out_size >= 1 + (long)NN * DD) {
        out_post = out + 1;
    }

    int nblk = 211 + (out_hid ? 208 : 0);
    k_setup<<<nblk, 512>>>(adj, obs, nW_in, nb_in, Wih1, bih1, post0, rew, hid0,
                           out_post, out_hid);
    k_stage1<<<352, 256>>>(hid0, Whh1, bhh1, lrp, out_hid);
    k_mid<<<12, 256>>>(post0, nW_hid, nb_hid, Wih2, bih2, Wih3, bih3, rew, out_post);
    dim3 g2(12, YB2);
    k_stage2<<<g2, 128>>>(hid0, Whh2, bhh2, lrp, out_hid);
    dim3 g3(12, 64);
    k_stage3<<<g3, 128>>>(hid0, Whh3, bhh3, lrp, nW_out, nb_out, Wih3,
                          out_hid, out_post, out_act);
}